// round 13
// baseline (speedup 1.0000x reference)
#include <cuda_runtime.h>
#include <math.h>
#include <stdint.h>

#define BT   4
#define LDIM 512
#define NF1  46
#define NF2  44
#define CCH  32
#define KD   64
#define PWROW 109      // F2D + 2*C + 1
#define PITCH 52       // 52 % 32 == 20 -> fragment rows hit 32 distinct banks

// ---------------- device scratch (no allocations allowed) ----------------
__device__ float g_x[BT*CCH*LDIM];
__device__ float g_y[BT*CCH*LDIM];
__device__ float g_embL[BT*LDIM*KD];
__device__ float g_embR[BT*LDIM*KD];
__device__ float g_peh[LDIM*32];
__device__ float g_sep[LDIM];
__device__ float2 g_Bfrag[8*6*32];   // [ntile][kstep][lane] -> (b0,b1), tf32 bits
__device__ int    g_ctr[40];         // per-bt barrier counters (bt*10 + stage)

__device__ __forceinline__ uint32_t f2tf32(float v) {
    uint32_t r;
    asm("cvt.rna.tf32.f32 %0, %1;" : "=r"(r) : "f"(v));
    return r;
}
__device__ __forceinline__ uint32_t smem_u32(const void* p) {
    uint32_t a;
    asm("{ .reg .u64 t; cvta.to.shared.u64 t, %1; cvt.u32.u64 %0, t; }" : "=r"(a) : "l"(p));
    return a;
}
#define CPASYNC(dst, src) asm volatile("cp.async.cg.shared.global [%0], [%1], 16;" :: "r"(dst), "l"(src))
#define CPCOMMIT()        asm volatile("cp.async.commit_group;" ::: "memory")
#define CPWAIT0()         asm volatile("cp.async.wait_group 0;" ::: "memory")

// ---------------- per-bt grid barrier (32 blocks of one bt) ----------------
__device__ __forceinline__ void bt_bar(int bt, int s, int tid) {
    __threadfence();
    __syncthreads();
    if (tid == 0) {
        int* ctr = &g_ctr[bt*10 + s];
        atomicAdd(ctr, 1);
        while (*(volatile int*)ctr < CCH) __nanosleep(20);
        __threadfence();
    }
    __syncthreads();
}

// ================= persistent trunk kernel =================
// grid (32, 4) = (channel, bt); 512 threads = l
__global__ __launch_bounds__(512) void trunk_kernel(
    const float* __restrict__ t1d,
    const float* __restrict__ p1w,
    const float* __restrict__ p1b,
    const float* __restrict__ c1w,
    const float* __restrict__ c2w,
    const float* __restrict__ proj_w)
{
    extern __shared__ float sIn[];      // 32*512 floats = 64KB
    __shared__ float swt[CCH*3];
    __shared__ float rs[16], rs2[16];
    __shared__ float smean, srstd;

    const int c = blockIdx.x, bt = blockIdx.y;
    const int t = threadIdx.x;
    const int bflat = bt*CCH + c;
    const int l = t;

    // ---- stage P: proj1d + independent precomputations ----
    {
        const float2* row = (const float2*)(t1d + (size_t)(bt*LDIM + l)*NF1);
        float acc = __ldg(&p1b[c]);
        #pragma unroll
        for (int f2 = 0; f2 < NF1/2; f2++) {
            float2 v = row[f2];
            acc = fmaf(__ldg(&p1w[c*NF1 + 2*f2]),     v.x, acc);
            acc = fmaf(__ldg(&p1w[c*NF1 + 2*f2 + 1]), v.y, acc);
        }
        g_x[(bt*CCH + c)*LDIM + l] = acc;

        // PE half table: 16384 entries, 128 per block
        if (t < 128) {
            int idx = bflat*128 + t;
            int ll = idx >> 5, m = idx & 31;
            int mm = m & 15;
            float dt = expf(-(float)(2*mm) * (logf(10000.f) / 32.f));
            float a = (float)ll * dt;
            g_peh[idx] = (m < 16) ? sinf(a) : cosf(a);
        }
        // B fragments (1536 entries): block 0
        if (bflat == 0) {
            #pragma unroll
            for (int k = 0; k < 3; k++) {
                int idx = k*512 + t;
                if (idx < 8*6*32) {
                    int nt = idx / (6*32);
                    int ks = (idx / 32) % 6;
                    int lane = idx & 31;
                    int o  = nt*8 + (lane >> 2);
                    int f0 = ks*8 + (lane & 3);
                    int f1 = f0 + 4;
                    float b0 = (f0 < NF2) ? proj_w[o*PWROW + f0] : 0.f;
                    float b1 = (f1 < NF2) ? proj_w[o*PWROW + f1] : 0.f;
                    float2 r;
                    r.x = __uint_as_float(f2tf32(b0));
                    r.y = __uint_as_float(f2tf32(b1));
                    g_Bfrag[idx] = r;
                }
            }
        }
        if (bflat == 1) g_sep[t] = logf((float)t + 1.f);
    }
    bt_bar(bt, 0, t);

    // ---- 8 conv + instance_norm (+residual) + elu stages ----
    for (int s = 0; s < 8; s++) {
        const int phase = s & 1;
        const float* in  = phase ? g_y : g_x;
        float*       outp = phase ? g_x : g_y;
        const float* w = (phase ? c2w : c1w) + (s >> 1)*CCH*CCH*3;

        if (t < CCH*3) swt[t] = w[c*CCH*3 + t];
        const float4* src = (const float4*)(in + bt*CCH*LDIM);
        #pragma unroll
        for (int k = 0; k < 8; k++)
            ((float4*)sIn)[t + k*512] = src[t + k*512];
        __syncthreads();

        float a4[4] = {0.f, 0.f, 0.f, 0.f};
        #pragma unroll 8
        for (int cp = 0; cp < CCH; cp++) {
            const float* r = sIn + cp*LDIM;
            float xm = (l > 0)        ? r[l-1] : 0.f;
            float x0 = r[l];
            float xp = (l < LDIM-1)   ? r[l+1] : 0.f;
            float tt = a4[cp & 3];
            tt = fmaf(swt[cp*3+0], xm, tt);
            tt = fmaf(swt[cp*3+1], x0, tt);
            tt = fmaf(swt[cp*3+2], xp, tt);
            a4[cp & 3] = tt;
        }
        float acc = (a4[0] + a4[1]) + (a4[2] + a4[3]);

        float ss = acc, s2 = acc*acc;
        #pragma unroll
        for (int off = 16; off > 0; off >>= 1) {
            ss += __shfl_xor_sync(0xffffffffu, ss, off);
            s2 += __shfl_xor_sync(0xffffffffu, s2, off);
        }
        int wid = t >> 5, lid = t & 31;
        if (lid == 0) { rs[wid] = ss; rs2[wid] = s2; }
        __syncthreads();
        if (wid == 0) {
            float aa  = (lid < 16) ? rs[lid]  : 0.f;
            float aa2 = (lid < 16) ? rs2[lid] : 0.f;
            #pragma unroll
            for (int off = 8; off > 0; off >>= 1) {
                aa  += __shfl_xor_sync(0xffffffffu, aa,  off);
                aa2 += __shfl_xor_sync(0xffffffffu, aa2, off);
            }
            if (lid == 0) {
                float mean = aa * (1.f/LDIM);
                float var  = aa2 * (1.f/LDIM) - mean*mean;
                smean = mean;
                srstd = rsqrtf(var + 1e-5f);
            }
        }
        __syncthreads();

        float v = (acc - smean) * srstd;
        if (phase) v += g_x[(bt*CCH + c)*LDIM + l];   // residual
        outp[(bt*CCH + c)*LDIM + l] = (v > 0.f) ? v : expm1f(v);

        bt_bar(bt, 1 + s, t);
    }

    // ---- final stage: embL / embR projections (2 outputs per thread) ----
    #pragma unroll
    for (int rr = 0; rr < 2; rr++) {
        int idx = bflat*1024 + rr*512 + t;
        int btx = idx >> 15;
        int rem = idx & 32767;
        int ll = rem >> 6, o = rem & 63;
        const float* xb = g_x + btx*CCH*LDIM;
        const float* pw = proj_w + o*PWROW;
        float aL = 0.f, aR = 0.f;
        #pragma unroll
        for (int cc = 0; cc < CCH; cc++) {
            float xv = xb[cc*LDIM + ll];
            aL = fmaf(__ldg(&pw[NF2 + cc]),       xv, aL);
            aR = fmaf(__ldg(&pw[NF2 + CCH + cc]), xv, aR);
        }
        g_embL[idx] = aL;
        g_embR[idx] = aR;
    }
}

// ================= pair kernel: j64 x o64 tiles, weights in registers =================
// grid (8, 128, 4) = (j-tile of 64, i-group of 4, bt); 256 threads = 8 warps
// warp = (jg, oh): jg = w&3 covers j rows [jg*16, jg*16+16); oh = w>>2 covers o [oh*32, oh*32+32)
__global__ __launch_bounds__(256, 3) void pair_mma_kernel(
    const float* __restrict__ t2d,
    const float* __restrict__ proj_w,
    const float* __restrict__ proj_b,
    float* __restrict__ out)
{
    extern __shared__ float dsm[];
    float* sA0 = dsm;                 // 64*PITCH floats
    float* sA1 = dsm + 64*PITCH;
    __shared__ float sWS[64], sPB[64];
    __shared__ float sSEP[LDIM];

    const int jt = blockIdx.x, ig = blockIdx.y, bt = blockIdx.z;
    const int j0 = jt * 64;
    const int tid = threadIdx.x;
    const int w   = tid >> 5, lane = tid & 31;
    const int jg  = w & 3, oh = w >> 2;
    const int g   = lane >> 2, tg = lane & 3;
    const int ocol = tg * 2;
    const bool usePE = (bt == 0);

    // ---- one-time block setup ----
    {
        const float4* ssrc = (const float4*)g_sep;
        float4* sdst = (float4*)sSEP;
        if (tid < 128) sdst[tid] = ssrc[tid];
    }
    if (tid < 64) {
        sWS[tid] = __ldg(&proj_w[tid*PWROW + (PWROW-1)]);
        sPB[tid] = __ldg(&proj_b[tid]);
    }
    if (tid < 128) {    // zero K-pad cols 44..47 in both buffers
        int b = tid >> 6, r = tid & 63;
        float* base = (b ? sA1 : sA0);
        *(float4*)&base[r*PITCH + 44] = make_float4(0.f, 0.f, 0.f, 0.f);
    }

    // weight B-fragments: cached in registers for this warp's o-half (o = oh*32 .. +31)
    float2 breg[4][6];
    #pragma unroll
    for (int nt = 0; nt < 4; nt++)
        #pragma unroll
        for (int ks = 0; ks < 6; ks++)
            breg[nt][ks] = __ldg(&g_Bfrag[((oh*4 + nt)*6 + ks)*32 + lane]);

    const uint32_t a0u = smem_u32(sA0);
    const uint32_t a1u = smem_u32(sA1);

    // tile 0 via cp.async: 64 rows x 44 floats = 704 float4
    {
        const float4* asrc = (const float4*)(t2d + ((size_t)((bt*LDIM + ig*4)*LDIM + j0)) * NF2);
        #pragma unroll
        for (int k = 0; k < 3; k++) {
            int e = tid + k*256;
            if (e < 704) {
                int row = e / 11, cc = (e - row*11)*4;
                CPASYNC(a0u + (uint32_t)(row*PITCH + cc)*4u, asrc + e);
            }
        }
        CPCOMMIT();
    }
    CPWAIT0();
    __syncthreads();

    #pragma unroll
    for (int ii = 0; ii < 4; ii++) {
        const int i = ig*4 + ii;
        const float* sA = (ii & 1) ? sA1 : sA0;

        // kick off next tile into the other buffer
        if (ii < 3) {
            uint32_t du = (ii & 1) ? a0u : a1u;
            const float4* ts = (const float4*)(t2d + ((size_t)((bt*LDIM + i + 1)*LDIM + j0)) * NF2);
            #pragma unroll
            for (int k = 0; k < 3; k++) {
                int e = tid + k*256;
                if (e < 704) {
                    int row = e / 11, cc = (e - row*11)*4;
                    CPASYNC(du + (uint32_t)(row*PITCH + cc)*4u, ts + e);
                }
            }
            CPCOMMIT();
        }

        // ---- MMA mainloop: A-frag LDS only; weights from registers ----
        float acc[4][4];
        #pragma unroll
        for (int nt = 0; nt < 4; nt++)
            #pragma unroll
            for (int q = 0; q < 4; q++) acc[nt][q] = 0.f;

        const float* Arow = sA + (jg*16 + g)*PITCH;
        #pragma unroll
        for (int ks = 0; ks < 6; ks++) {
            uint32_t a0 = f2tf32(Arow[ks*8 + tg]);
            uint32_t a1 = f2tf32(Arow[8*PITCH + ks*8 + tg]);
            uint32_t a2 = f2tf32(Arow[ks*8 + tg + 4]);
            uint32_t a3 = f2tf32(Arow[8*PITCH + ks*8 + tg + 4]);
            #pragma unroll
            for (int nt = 0; nt < 4; nt++) {
                uint32_t b0 = __float_as_uint(breg[nt][ks].x);
                uint32_t b1 = __float_as_uint(breg[nt][ks].y);
                asm volatile(
                    "mma.sync.aligned.m16n8k8.row.col.f32.tf32.tf32.f32 "
                    "{%0,%1,%2,%3}, {%4,%5,%6,%7}, {%8,%9}, {%0,%1,%2,%3};"
                    : "+f"(acc[nt][0]), "+f"(acc[nt][1]), "+f"(acc[nt][2]), "+f"(acc[nt][3])
                    : "r"(a0), "r"(a1), "r"(a2), "r"(a3), "r"(b0), "r"(b1));
            }
        }

        // ---- fused epilogue ----
        const float* elrow  = g_embL + ((size_t)(bt*LDIM + i))*64;
        const float* peirow = g_peh + i*32;
        float cbx[4], cby[4];
        #pragma unroll
        for (int nt = 0; nt < 4; nt++) {
            int o = oh*32 + nt*8 + ocol;
            float2 el = *(const float2*)(elrow + o);
            cbx[nt] = el.x + sPB[o];
            cby[nt] = el.y + sPB[o+1];
            if (usePE && oh == 0) {      // o < 32: i-row PE
                float2 p = *(const float2*)(peirow + o);
                cbx[nt] += p.x; cby[nt] += p.y;
            }
        }
        #pragma unroll
        for (int h = 0; h < 2; h++) {
            const int j = j0 + jg*16 + g + h*8;
            int dd = i - j; if (dd < 0) dd = -dd;
            const float sep = sSEP[dd];
            const float* erow = g_embR + ((size_t)(bt*LDIM + j))*64;
            float* orow = out + ((size_t)((bt*LDIM + i)*LDIM + j))*64;
            const float* prow = g_peh + j*32;
            #pragma unroll
            for (int nt = 0; nt < 4; nt++) {
                const int o = oh*32 + nt*8 + ocol;
                float2 er = *(const float2*)(erow + o);
                float v0 = acc[nt][h*2+0] + cbx[nt] + er.x + sep*sWS[o];
                float v1 = acc[nt][h*2+1] + cby[nt] + er.y + sep*sWS[o+1];
                if (usePE && oh == 1) {  // o >= 32: j-row PE
                    float2 p = *(const float2*)(prow + (o - 32));
                    v0 += p.x; v1 += p.y;
                }
                float2 ov; ov.x = v0; ov.y = v1;
                *(float2*)(orow + o) = ov;
            }
        }

        if (ii < 3) {
            CPWAIT0();
            __syncthreads();
        }
    }
}

// ---------------- launch ----------------
extern "C" void kernel_launch(void* const* d_in, const int* in_sizes, int n_in,
                              void* d_out, int out_size) {
    const float* t1d = (const float*)d_in[0];
    const float* t2d = (const float*)d_in[1];
    const float* p1w = (const float*)d_in[2];
    const float* p1b = (const float*)d_in[3];
    const float* c1w = (const float*)d_in[4];
    const float* c2w = (const float*)d_in[5];
    const float* pw  = (const float*)d_in[6];
    const float* pb  = (const float*)d_in[7];
    float* out = (float*)d_out;

    const int trunkSmem = CCH*LDIM*sizeof(float);          // 64 KB
    const int pairSmem  = (2*64*PITCH)*sizeof(float);      // 26624 B
    cudaFuncSetAttribute(trunk_kernel,
                         cudaFuncAttributeMaxDynamicSharedMemorySize, trunkSmem);
    cudaFuncSetAttribute(pair_mma_kernel,
                         cudaFuncAttributeMaxDynamicSharedMemorySize, pairSmem);

    void* ctrPtr = nullptr;
    cudaGetSymbolAddress(&ctrPtr, g_ctr);
    cudaMemsetAsync(ctrPtr, 0, 40*sizeof(int));

    trunk_kernel<<<dim3(CCH, BT), 512, trunkSmem>>>(t1d, p1w, p1b, c1w, c2w, pw);
    pair_mma_kernel<<<dim3(8, LDIM/4, BT), 256, pairSmem>>>(t2d, pw, pb, out);
}

// round 14
// speedup vs baseline: 1.0343x; 1.0343x over previous
#include <cuda_runtime.h>
#include <math.h>
#include <stdint.h>

#define BT   4
#define LDIM 512
#define NF1  46
#define NF2  44
#define CCH  32
#define KD   64
#define PWROW 109      // F2D + 2*C + 1
#define PITCH 52       // 52 % 32 == 20 -> fragment rows hit 32 distinct banks

// ---------------- device scratch (no allocations allowed) ----------------
__device__ float g_x[BT*CCH*LDIM];
__device__ float g_y[BT*CCH*LDIM];
__device__ float g_embL[BT*LDIM*KD];
__device__ float g_embR[BT*LDIM*KD];
__device__ float g_peh[LDIM*32];
__device__ float g_sep[LDIM];
__device__ float2 g_Bfrag[8*6*32];   // [ntile][kstep][lane] -> (b0,b1), tf32 bits
__device__ int    g_ctr[40];         // sense-reversing barrier counters (self-resetting)
__device__ int    g_flag[40];        // sense flags (toggle once per barrier use)

__device__ __forceinline__ uint32_t f2tf32(float v) {
    uint32_t r;
    asm("cvt.rna.tf32.f32 %0, %1;" : "=r"(r) : "f"(v));
    return r;
}
__device__ __forceinline__ uint32_t smem_u32(const void* p) {
    uint32_t a;
    asm("{ .reg .u64 t; cvta.to.shared.u64 t, %1; cvt.u32.u64 %0, t; }" : "=r"(a) : "l"(p));
    return a;
}
#define CPASYNC(dst, src) asm volatile("cp.async.cg.shared.global [%0], [%1], 16;" :: "r"(dst), "l"(src))
#define CPCOMMIT()        asm volatile("cp.async.commit_group;" ::: "memory")
#define CPWAIT0()         asm volatile("cp.async.wait_group 0;" ::: "memory")

// ---------------- per-bt sense-reversing barrier (32 blocks of one bt) ----------------
// No threadfence, no nanosleep, no host-side reset: counter self-resets, flag toggles.
__device__ __forceinline__ void bt_bar(int bt, int s, int tid) {
    __syncthreads();
    if (tid == 0) {
        int* ctr = &g_ctr[bt*10 + s];
        int* flg = &g_flag[bt*10 + s];
        int sense;
        asm volatile("ld.acquire.gpu.global.s32 %0, [%1];" : "=r"(sense) : "l"(flg));
        int old;
        asm volatile("atom.acq_rel.gpu.global.add.s32 %0, [%1], 1;" : "=r"(old) : "l"(ctr) : "memory");
        if (old == CCH - 1) {
            asm volatile("st.relaxed.gpu.global.s32 [%0], %1;" :: "l"(ctr), "r"(0) : "memory");
            asm volatile("st.release.gpu.global.s32 [%0], %1;" :: "l"(flg), "r"(sense ^ 1) : "memory");
        } else {
            int v;
            do {
                asm volatile("ld.acquire.gpu.global.s32 %0, [%1];" : "=r"(v) : "l"(flg));
            } while (v == sense);
        }
    }
    __syncthreads();
}

// ================= persistent trunk kernel =================
// grid (32, 4) = (channel, bt); 512 threads = l
__global__ __launch_bounds__(512) void trunk_kernel(
    const float* __restrict__ t1d,
    const float* __restrict__ p1w,
    const float* __restrict__ p1b,
    const float* __restrict__ c1w,
    const float* __restrict__ c2w,
    const float* __restrict__ proj_w)
{
    extern __shared__ float sIn[];      // 32*512 floats = 64KB
    __shared__ float swt[CCH*3];
    __shared__ float rs[16], rs2[16];
    __shared__ float smean, srstd;

    const int c = blockIdx.x, bt = blockIdx.y;
    const int t = threadIdx.x;
    const int bflat = bt*CCH + c;
    const int l = t;

    // ---- stage P: proj1d + independent precomputations ----
    {
        const float2* row = (const float2*)(t1d + (size_t)(bt*LDIM + l)*NF1);
        float acc = __ldg(&p1b[c]);
        #pragma unroll
        for (int f2 = 0; f2 < NF1/2; f2++) {
            float2 v = row[f2];
            acc = fmaf(__ldg(&p1w[c*NF1 + 2*f2]),     v.x, acc);
            acc = fmaf(__ldg(&p1w[c*NF1 + 2*f2 + 1]), v.y, acc);
        }
        g_x[(bt*CCH + c)*LDIM + l] = acc;

        // PE half table: 16384 entries, 128 per block
        if (t < 128) {
            int idx = bflat*128 + t;
            int ll = idx >> 5, m = idx & 31;
            int mm = m & 15;
            float dt = expf(-(float)(2*mm) * (logf(10000.f) / 32.f));
            float a = (float)ll * dt;
            g_peh[idx] = (m < 16) ? sinf(a) : cosf(a);
        }
        // B fragments (1536 entries): block 0
        if (bflat == 0) {
            #pragma unroll
            for (int k = 0; k < 3; k++) {
                int idx = k*512 + t;
                if (idx < 8*6*32) {
                    int nt = idx / (6*32);
                    int ks = (idx / 32) % 6;
                    int lane = idx & 31;
                    int o  = nt*8 + (lane >> 2);
                    int f0 = ks*8 + (lane & 3);
                    int f1 = f0 + 4;
                    float b0 = (f0 < NF2) ? proj_w[o*PWROW + f0] : 0.f;
                    float b1 = (f1 < NF2) ? proj_w[o*PWROW + f1] : 0.f;
                    float2 r;
                    r.x = __uint_as_float(f2tf32(b0));
                    r.y = __uint_as_float(f2tf32(b1));
                    g_Bfrag[idx] = r;
                }
            }
        }
        if (bflat == 1) g_sep[t] = logf((float)t + 1.f);
    }
    bt_bar(bt, 0, t);

    // ---- 8 conv + instance_norm (+residual) + elu stages ----
    for (int s = 0; s < 8; s++) {
        const int phase = s & 1;
        const float* in  = phase ? g_y : g_x;
        float*       outp = phase ? g_x : g_y;
        const float* w = (phase ? c2w : c1w) + (s >> 1)*CCH*CCH*3;

        if (t < CCH*3) swt[t] = w[c*CCH*3 + t];
        const float4* src = (const float4*)(in + bt*CCH*LDIM);
        #pragma unroll
        for (int k = 0; k < 8; k++)
            ((float4*)sIn)[t + k*512] = src[t + k*512];
        __syncthreads();

        float a4[4] = {0.f, 0.f, 0.f, 0.f};
        #pragma unroll 8
        for (int cp = 0; cp < CCH; cp++) {
            const float* r = sIn + cp*LDIM;
            float xm = (l > 0)        ? r[l-1] : 0.f;
            float x0 = r[l];
            float xp = (l < LDIM-1)   ? r[l+1] : 0.f;
            float tt = a4[cp & 3];
            tt = fmaf(swt[cp*3+0], xm, tt);
            tt = fmaf(swt[cp*3+1], x0, tt);
            tt = fmaf(swt[cp*3+2], xp, tt);
            a4[cp & 3] = tt;
        }
        float acc = (a4[0] + a4[1]) + (a4[2] + a4[3]);

        float ss = acc, s2 = acc*acc;
        #pragma unroll
        for (int off = 16; off > 0; off >>= 1) {
            ss += __shfl_xor_sync(0xffffffffu, ss, off);
            s2 += __shfl_xor_sync(0xffffffffu, s2, off);
        }
        int wid = t >> 5, lid = t & 31;
        if (lid == 0) { rs[wid] = ss; rs2[wid] = s2; }
        __syncthreads();
        if (wid == 0) {
            float aa  = (lid < 16) ? rs[lid]  : 0.f;
            float aa2 = (lid < 16) ? rs2[lid] : 0.f;
            #pragma unroll
            for (int off = 8; off > 0; off >>= 1) {
                aa  += __shfl_xor_sync(0xffffffffu, aa,  off);
                aa2 += __shfl_xor_sync(0xffffffffu, aa2, off);
            }
            if (lid == 0) {
                float mean = aa * (1.f/LDIM);
                float var  = aa2 * (1.f/LDIM) - mean*mean;
                smean = mean;
                srstd = rsqrtf(var + 1e-5f);
            }
        }
        __syncthreads();

        float v = (acc - smean) * srstd;
        if (phase) v += g_x[(bt*CCH + c)*LDIM + l];   // residual
        outp[(bt*CCH + c)*LDIM + l] = (v > 0.f) ? v : expm1f(v);

        bt_bar(bt, 1 + s, t);
    }

    // ---- final stage: embL / embR projections (2 outputs per thread) ----
    #pragma unroll
    for (int rr = 0; rr < 2; rr++) {
        int idx = bflat*1024 + rr*512 + t;
        int btx = idx >> 15;
        int rem = idx & 32767;
        int ll = rem >> 6, o = rem & 63;
        const float* xb = g_x + btx*CCH*LDIM;
        const float* pw = proj_w + o*PWROW;
        float aL = 0.f, aR = 0.f;
        #pragma unroll
        for (int cc = 0; cc < CCH; cc++) {
            float xv = xb[cc*LDIM + ll];
            aL = fmaf(__ldg(&pw[NF2 + cc]),       xv, aL);
            aR = fmaf(__ldg(&pw[NF2 + CCH + cc]), xv, aR);
        }
        g_embL[idx] = aL;
        g_embR[idx] = aR;
    }
}

// ================= pair kernel (R12 layout, i-group 8) =================
// grid (4, 64, 4) = (j-tile of 128, i-group of 8, bt); 256 threads = 8 warps
// warp w covers j rows [w*16, w*16+16), all 8 n-tiles of 8 o; K = 48 (6 k-steps)
__global__ __launch_bounds__(256, 3) void pair_mma_kernel(
    const float* __restrict__ t2d,
    const float* __restrict__ proj_w,
    const float* __restrict__ proj_b,
    float* __restrict__ out)
{
    extern __shared__ float dsm[];
    float*  sA0 = dsm;                            // 128*PITCH floats
    float*  sA1 = dsm + 128*PITCH;
    float2* sB  = (float2*)(dsm + 2*128*PITCH);   // 8*6*32 float2 = 12288 B
    __shared__ float sWS[64], sPB[64];
    __shared__ float sSEP[LDIM];

    const int jt = blockIdx.x, ig = blockIdx.y, bt = blockIdx.z;
    const int j0 = jt * 128;
    const int tid = threadIdx.x;
    const int w   = tid >> 5, lane = tid & 31;

    // one-time: B fragments + per-o consts + sep table + K-pad zeros
    {
        const float4* bs = (const float4*)g_Bfrag;
        float4* bd = (float4*)sB;
        #pragma unroll
        for (int k = 0; k < 3; k++) bd[tid + k*256] = bs[tid + k*256];
    }
    {
        const float4* ssrc = (const float4*)g_sep;
        float4* sdst = (float4*)sSEP;
        if (tid < 128) sdst[tid] = ssrc[tid];
    }
    if (tid < 64) {
        sWS[tid] = __ldg(&proj_w[tid*PWROW + (PWROW-1)]);
        sPB[tid] = __ldg(&proj_b[tid]);
    }
    if (tid < 128) {
        *(float4*)&sA0[tid*PITCH + 44] = make_float4(0.f, 0.f, 0.f, 0.f);
        *(float4*)&sA1[tid*PITCH + 44] = make_float4(0.f, 0.f, 0.f, 0.f);
    }

    const uint32_t a0u = smem_u32(sA0);
    const uint32_t a1u = smem_u32(sA1);

    // tile 0 via cp.async
    {
        const float4* asrc = (const float4*)(t2d + ((size_t)((bt*LDIM + ig*8)*LDIM + j0)) * NF2);
        #pragma unroll
        for (int k = 0; k < 6; k++) {
            int e = tid + k*256;
            if (e < 1408) {
                int row = e / 11, cc = (e - row*11)*4;
                CPASYNC(a0u + (uint32_t)(row*PITCH + cc)*4u, asrc + e);
            }
        }
        CPCOMMIT();
    }
    CPWAIT0();
    __syncthreads();

    const int g = lane >> 2;        // row within frag
    const int tg = lane & 3;        // thread in group
    const int ocol = tg * 2;
    const bool usePE = (bt == 0);

    #pragma unroll 2
    for (int ii = 0; ii < 8; ii++) {
        const int i = ig*8 + ii;
        const float* sA = (ii & 1) ? sA1 : sA0;

        // kick off next tile into the other buffer
        if (ii < 7) {
            uint32_t du = (ii & 1) ? a0u : a1u;
            const float4* ts = (const float4*)(t2d + ((size_t)((bt*LDIM + i + 1)*LDIM + j0)) * NF2);
            #pragma unroll
            for (int k = 0; k < 6; k++) {
                int e = tid + k*256;
                if (e < 1408) {
                    int row = e / 11, cc = (e - row*11)*4;
                    CPASYNC(du + (uint32_t)(row*PITCH + cc)*4u, ts + e);
                }
            }
            CPCOMMIT();
        }

        // ---- MMA mainloop ----
        float acc[8][4];
        #pragma unroll
        for (int nt = 0; nt < 8; nt++)
            #pragma unroll
            for (int q = 0; q < 4; q++) acc[nt][q] = 0.f;

        const float* Arow = sA + (w*16 + g)*PITCH;
        #pragma unroll
        for (int ks = 0; ks < 6; ks++) {
            uint32_t a0 = f2tf32(Arow[ks*8 + tg]);
            uint32_t a1 = f2tf32(Arow[8*PITCH + ks*8 + tg]);
            uint32_t a2 = f2tf32(Arow[ks*8 + tg + 4]);
            uint32_t a3 = f2tf32(Arow[8*PITCH + ks*8 + tg + 4]);
            #pragma unroll
            for (int nt = 0; nt < 8; nt++) {
                float2 bb = sB[(nt*6 + ks)*32 + lane];
                uint32_t b0 = __float_as_uint(bb.x);
                uint32_t b1 = __float_as_uint(bb.y);
                asm volatile(
                    "mma.sync.aligned.m16n8k8.row.col.f32.tf32.tf32.f32 "
                    "{%0,%1,%2,%3}, {%4,%5,%6,%7}, {%8,%9}, {%0,%1,%2,%3};"
                    : "+f"(acc[nt][0]), "+f"(acc[nt][1]), "+f"(acc[nt][2]), "+f"(acc[nt][3])
                    : "r"(a0), "r"(a1), "r"(a2), "r"(a3), "r"(b0), "r"(b1));
            }
        }

        // ---- fused epilogue ----
        const float* elrow  = g_embL + ((size_t)(bt*LDIM + i))*64;
        const float* peirow = g_peh + i*32;
        float cbx[8], cby[8];
        #pragma unroll
        for (int nt = 0; nt < 8; nt++) {
            int o = nt*8 + ocol;
            float2 el = *(const float2*)(elrow + o);
            cbx[nt] = el.x + sPB[o];
            cby[nt] = el.y + sPB[o+1];
            if (usePE && nt < 4) {
                float2 p = *(const float2*)(peirow + o);
                cbx[nt] += p.x; cby[nt] += p.y;
            }
        }
        #pragma unroll
        for (int h = 0; h < 2; h++) {
            const int j = j0 + w*16 + g + h*8;
            int dd = i - j; if (dd < 0) dd = -dd;
            const float sep = sSEP[dd];
            const float* erow = g_embR + ((size_t)(bt*LDIM + j))*64;
            float* orow = out + ((size_t)((bt*LDIM + i)*LDIM + j))*64;
            const float* prow = g_peh + j*32;
            #pragma unroll
            for (int nt = 0; nt < 8; nt++) {
                const int o = nt*8 + ocol;
                float2 er = *(const float2*)(erow + o);
                float v0 = acc[nt][h*2+0] + cbx[nt] + er.x + sep*sWS[o];
                float v1 = acc[nt][h*2+1] + cby[nt] + er.y + sep*sWS[o+1];
                if (usePE && nt >= 4) {
                    float2 p = *(const float2*)(prow + (o - 32));
                    v0 += p.x; v1 += p.y;
                }
                float2 ov; ov.x = v0; ov.y = v1;
                *(float2*)(orow + o) = ov;
            }
        }

        if (ii < 7) {
            CPWAIT0();
            __syncthreads();
        }
    }
}

// ---------------- launch ----------------
extern "C" void kernel_launch(void* const* d_in, const int* in_sizes, int n_in,
                              void* d_out, int out_size) {
    const float* t1d = (const float*)d_in[0];
    const float* t2d = (const float*)d_in[1];
    const float* p1w = (const float*)d_in[2];
    const float* p1b = (const float*)d_in[3];
    const float* c1w = (const float*)d_in[4];
    const float* c2w = (const float*)d_in[5];
    const float* pw  = (const float*)d_in[6];
    const float* pb  = (const float*)d_in[7];
    float* out = (float*)d_out;

    const int trunkSmem = CCH*LDIM*sizeof(float);              // 64 KB
    const int pairSmem  = (2*128*PITCH)*sizeof(float) + 12288; // 65536 B
    cudaFuncSetAttribute(trunk_kernel,
                         cudaFuncAttributeMaxDynamicSharedMemorySize, trunkSmem);
    cudaFuncSetAttribute(pair_mma_kernel,
                         cudaFuncAttributeMaxDynamicSharedMemorySize, pairSmem);

    trunk_kernel<<<dim3(CCH, BT), 512, trunkSmem>>>(t1d, p1w, p1b, c1w, c2w, pw);
    pair_mma_kernel<<<dim3(4, LDIM/8, BT), 256, pairSmem>>>(t2d, pw, pb, out);
}